// round 1
// baseline (speedup 1.0000x reference)
#include <cuda_runtime.h>
#include <cstdint>

// ---------------------------------------------------------------------------
// Problem constants (fixed shapes from setup_inputs)
// ---------------------------------------------------------------------------
#define B_       8
#define C_       256
#define H_       32
#define W_       32
#define HW_      1024
#define NOBJ     16
#define P_       7
#define PQ_      49
#define NROI_OBJ 128            // B_*NOBJ
#define NPAIR    256            // NOBJ*NOBJ
#define NROI_UN  2048           // B_*NPAIR
#define CREL     384            // C/2*3
#define D1_      256
#define D2_      256
#define KOBJ     512            // 2*C
#define KREL     896            // 2*D1 + CREL
#define NPQ_OBJ  (NROI_OBJ*PQ_) // 6272
#define NPQ_UN   (NROI_UN*PQ_)  // 100352
#define KFC      (256*PQ_)      // 12544
#define NROI_TOT (1 + NROI_OBJ + NROI_UN) // img + obj + union = 2177
#define OBJ_OUT_SZ (NROI_OBJ*D1_)         // 32768

// ---------------------------------------------------------------------------
// Device scratch (static allocations only — no cudaMalloc allowed)
// ---------------------------------------------------------------------------
__device__ float g_ctx     [B_*C_*HW_];          // ctx conv output
__device__ float g_relf    [B_*CREL*HW_];        // rel conv output
__device__ float g_wx      [NROI_TOT*P_*W_];     // per-ROI x weights [roi][p][i]
__device__ float g_wy      [NROI_TOT*P_*H_];     // per-ROI y weights
__device__ float g_inv_area[NROI_TOT];
__device__ float g_ctx_pool[B_*C_*PQ_];          // pooled ctx (already /area)
__device__ float g_box_imap[NROI_OBJ*PQ_];
__device__ float g_sub_imap[NROI_UN*PQ_];
__device__ float g_obj_imap[NROI_UN*PQ_];
__device__ float g_obj_in  [(size_t)KOBJ*NPQ_OBJ];   // [512][6272]
__device__ float g_obj_feat[(size_t)D1_*NPQ_OBJ];    // [256][6272]
__device__ float g_rel_in  [(size_t)KREL*NPQ_UN];    // [896][100352]
__device__ float g_rel_feat[(size_t)D2_*NPQ_UN];     // [256][100352]
__device__ float g_act_obj [(size_t)KFC*NROI_OBJ];   // [12544][128]
__device__ float g_act_rel [(size_t)KFC*NROI_UN];    // [12544][2048]
__device__ float g_out_obj [(size_t)D1_*NROI_OBJ];   // [256][128]
__device__ float g_out_rel [(size_t)D2_*NROI_UN];    // [256][2048]

// ---------------------------------------------------------------------------
// Helpers
// ---------------------------------------------------------------------------
__device__ __forceinline__ float hat_int(float t) {
    t = fminf(fmaxf(t, -1.f), 1.f);
    float u  = 1.f - t;
    float r0 = 0.5f * (t + 1.f) * (t + 1.f);
    float r1 = 1.f - 0.5f * u * u;
    return (t < 0.f) ? r0 : r1;
}

__device__ __forceinline__ float imap_frac(float b1x0, float b1y0, float b1x1, float b1y1,
                                           float b2x0, float b2y0, float b2x1, float b2y1,
                                           int p, int q) {
    float bw = (b2x1 - b2x0) / 7.f;
    float bh = (b2y1 - b2y0) / 7.f;
    float gx0 = b2x0 + bw * (float)q;
    float gy0 = b2y0 + bh * (float)p;
    float ox = fmaxf(0.f, fminf(gx0 + bw, b1x1) - fmaxf(gx0, b1x0));
    float oy = fmaxf(0.f, fminf(gy0 + bh, b1y1) - fmaxf(gy0, b1y0));
    return oy * ox / fmaxf(bw * bh, 1e-8f);
}

// ---------------------------------------------------------------------------
// ROI integration weights: roi 0 = image box, 1..128 = object boxes,
// 129..2176 = union boxes.
// ---------------------------------------------------------------------------
__global__ void k_roi_weights(const float* __restrict__ objects) {
    int roi = blockIdx.x;
    float b0, b1, b2, b3;
    if (roi == 0) {
        b0 = 0.f; b1 = 0.f; b2 = 512.f; b3 = 512.f;
    } else if (roi <= NROI_OBJ) {
        const float* o = objects + (roi - 1) * 4;
        b0 = o[0]; b1 = o[1]; b2 = o[2]; b3 = o[3];
    } else {
        int u  = roi - (1 + NROI_OBJ);
        int b  = u / NPAIR;
        int pi = u % NPAIR;
        int i  = pi / NOBJ, j = pi % NOBJ;
        const float* s = objects + (b * NOBJ + i) * 4;
        const float* o = objects + (b * NOBJ + j) * 4;
        b0 = fminf(s[0], o[0]); b1 = fminf(s[1], o[1]);
        b2 = fmaxf(s[2], o[2]); b3 = fmaxf(s[3], o[3]);
    }
    const float sc = 1.f / 16.f;
    float lx = b0 * sc, hx = b2 * sc, ly = b1 * sc, hy = b3 * sc;
    float bwx = (hx - lx) / 7.f;
    float bwy = (hy - ly) / 7.f;
    int t = threadIdx.x;
    if (t < P_ * 32) {
        int p = t / 32, i = t % 32;
        float sx = lx + bwx * (float)p, ex = sx + bwx;
        g_wx[roi * (P_ * 32) + t] = hat_int(ex - (float)i) - hat_int(sx - (float)i);
        float sy = ly + bwy * (float)p, ey = sy + bwy;
        g_wy[roi * (P_ * 32) + t] = hat_int(ey - (float)i) - hat_int(sy - (float)i);
    }
    if (t == 0) g_inv_area[roi] = 1.f / fmaxf(bwx * bwy, 1e-8f);
}

// ---------------------------------------------------------------------------
// Intersection maps. Blocks 0..127: object box vs image grid.
// Blocks 128..2175: sub & obj box vs union grid.
// ---------------------------------------------------------------------------
__global__ void k_imaps(const float* __restrict__ objects) {
    int bid = blockIdx.x;
    int t = threadIdx.x;
    if (t >= PQ_) return;
    int p = t / P_, q = t % P_;
    if (bid < NROI_OBJ) {
        const float* o = objects + bid * 4;
        g_box_imap[bid * PQ_ + t] =
            imap_frac(o[0], o[1], o[2], o[3], 0.f, 0.f, 512.f, 512.f, p, q);
    } else {
        int u  = bid - NROI_OBJ;
        int b  = u / NPAIR;
        int pi = u % NPAIR;
        int i  = pi / NOBJ, j = pi % NOBJ;
        const float* s = objects + (b * NOBJ + i) * 4;
        const float* o = objects + (b * NOBJ + j) * 4;
        float ux0 = fminf(s[0], o[0]), uy0 = fminf(s[1], o[1]);
        float ux1 = fmaxf(s[2], o[2]), uy1 = fmaxf(s[3], o[3]);
        g_sub_imap[u * PQ_ + t] =
            imap_frac(s[0], s[1], s[2], s[3], ux0, uy0, ux1, uy1, p, q);
        g_obj_imap[u * PQ_ + t] =
            imap_frac(o[0], o[1], o[2], o[3], ux0, uy0, ux1, uy1, p, q);
    }
}

// ---------------------------------------------------------------------------
// Separable PrRoI pooling core: loads one [32][32] channel tile to SMEM,
// contracts with wy (-> tmp[7][32]) then wx (-> 49 outputs).
// ---------------------------------------------------------------------------
__device__ __forceinline__ float pool_stage(const float* __restrict__ feat_base,
                                            int roi, float* tile, float* swy,
                                            float* swx, float* tmp) {
    int t = threadIdx.x; // 224 threads
    for (int i = t; i < HW_; i += 224) tile[i] = feat_base[i];
    swy[t] = g_wy[roi * 224 + t];
    swx[t] = g_wx[roi * 224 + t];
    __syncthreads();
    {
        int p = t / 32, w = t % 32;
        float s = 0.f;
        #pragma unroll 8
        for (int h = 0; h < 32; h++) s += tile[h * 32 + w] * swy[p * 32 + h];
        tmp[t] = s;
    }
    __syncthreads();
    float r = 0.f;
    if (t < PQ_) {
        int p = t / P_, q = t % P_;
        #pragma unroll 8
        for (int w = 0; w < 32; w++) r += tmp[p * 32 + w] * swx[q * 32 + w];
    }
    return r;
}

// Context pool over the image box: blockIdx.x = b*C + c
__global__ void k_ctx_pool() {
    __shared__ float tile[HW_], swy[224], swx[224], tmp[224];
    int bc = blockIdx.x;
    float r = pool_stage(g_ctx + (size_t)bc * HW_, 0, tile, swy, swx, tmp);
    if (threadIdx.x < PQ_)
        g_ctx_pool[(size_t)bc * PQ_ + threadIdx.x] = r * g_inv_area[0];
}

// Object pooling of raw input: blockIdx.x = rg*C + c, writes g_obj_in rows 0..255
__global__ void k_obj_pool(const float* __restrict__ input) {
    __shared__ float tile[HW_], swy[224], swx[224], tmp[224];
    int rg = blockIdx.x / C_;
    int c  = blockIdx.x % C_;
    int b  = rg / NOBJ;
    float r = pool_stage(input + ((size_t)b * C_ + c) * HW_, 1 + rg, tile, swy, swx, tmp);
    if (threadIdx.x < PQ_)
        g_obj_in[(size_t)c * NPQ_OBJ + rg * PQ_ + threadIdx.x] = r * g_inv_area[1 + rg];
}

// Union pooling of rel features: blockIdx.x = ru*CREL + c,
// writes g_rel_in rows 512..895 with imap scaling baked in.
__global__ void k_rel_pool() {
    __shared__ float tile[HW_], swy[224], swx[224], tmp[224];
    int ru = blockIdx.x / CREL;
    int c  = blockIdx.x % CREL;
    int b  = ru / NPAIR;
    float r = pool_stage(g_relf + ((size_t)b * CREL + c) * HW_, 1 + NROI_OBJ + ru,
                         tile, swy, swx, tmp);
    int t = threadIdx.x;
    if (t < PQ_) {
        float v = r * g_inv_area[1 + NROI_OBJ + ru];
        if (c >= 256)      v *= g_obj_imap[ru * PQ_ + t];
        else if (c >= 128) v *= g_sub_imap[ru * PQ_ + t];
        g_rel_in[((size_t)(512 + c)) * NPQ_UN + ru * PQ_ + t] = v;
    }
}

// Fill g_obj_in rows 256..511 from ctx_pool (+ box_imap for y half)
__global__ void k_fill_obj_ctx() {
    int idx = blockIdx.x * blockDim.x + threadIdx.x;
    if (idx >= 256 * NPQ_OBJ) return;
    int c2 = idx / NPQ_OBJ;
    int nn = idx % NPQ_OBJ;
    int rg = nn / PQ_, pq = nn % PQ_;
    int b  = rg / NOBJ;
    float v = g_ctx_pool[((size_t)b * C_ + c2) * PQ_ + pq];
    if (c2 >= 128) v *= g_box_imap[rg * PQ_ + pq];
    g_obj_in[((size_t)(256 + c2)) * NPQ_OBJ + nn] = v;
}

// Gather obj_feat[sub]/obj_feat[obj] into g_rel_in rows 0..511
__global__ void k_gather_objfeat() {
    size_t idx = (size_t)blockIdx.x * blockDim.x + threadIdx.x;
    if (idx >= (size_t)512 * NPQ_UN) return;
    int d2 = (int)(idx / NPQ_UN);
    int nu = (int)(idx % NPQ_UN);
    int ru = nu / PQ_, pq = nu % PQ_;
    int b  = ru / NPAIR;
    int pi = ru % NPAIR;
    int r  = (d2 < 256) ? (pi / NOBJ) : (pi % NOBJ);
    int d  = d2 & 255;
    g_rel_in[idx] = g_obj_feat[(size_t)d * NPQ_OBJ + (b * NOBJ + r) * PQ_ + pq];
}

// ReLU + transpose repack: in [256][R*49] -> out [256*49][R]
__global__ void k_repack(const float* __restrict__ in, float* __restrict__ out, int R) {
    __shared__ float s[32 * PQ_];
    int d  = blockIdx.x;
    int r0 = blockIdx.y * 32;
    const float* src = in + (size_t)d * R * PQ_ + (size_t)r0 * PQ_;
    for (int i = threadIdx.x; i < 32 * PQ_; i += blockDim.x)
        s[i] = fmaxf(0.f, src[i]);
    __syncthreads();
    for (int i = threadIdx.x; i < 32 * PQ_; i += blockDim.x) {
        int pq = i / 32, r = i % 32;
        out[((size_t)d * PQ_ + pq) * R + r0 + r] = s[r * PQ_ + pq];
    }
}

// L2 normalize columns of M[256][R] and write rows [r][256] to out
__global__ void k_normalize(const float* __restrict__ M, float* __restrict__ out, int R) {
    __shared__ float red[256];
    int r = blockIdx.x;
    int e = threadIdx.x;
    float v = M[(size_t)e * R + r];
    red[e] = v * v;
    __syncthreads();
    for (int s = 128; s > 0; s >>= 1) {
        if (e < s) red[e] += red[e + s];
        __syncthreads();
    }
    out[(size_t)r * 256 + e] = v * rsqrtf(red[0]);
}

// ---------------------------------------------------------------------------
// Tiled fp32 GEMM: C[M][N] = A[M][K] * B[K][N] + bias[M]
// 64x64 tile, BK=16, 256 threads, 4x4 per thread. K must be multiple of 16.
// Batched via blockIdx.z (A shared across batch).
// ---------------------------------------------------------------------------
__global__ void sgemm(const float* __restrict__ A, const float* __restrict__ B,
                      const float* __restrict__ bias, float* __restrict__ C,
                      int M, int N, int K, long long strideB, long long strideC) {
    const float* Bz = B + (long long)blockIdx.z * strideB;
    float*       Cz = C + (long long)blockIdx.z * strideC;
    __shared__ float As[64][16];
    __shared__ float Bs[16][64];
    int row0 = blockIdx.y * 64, col0 = blockIdx.x * 64;
    int tid = threadIdx.x;
    float acc[4][4];
    #pragma unroll
    for (int i = 0; i < 4; i++)
        #pragma unroll
        for (int j = 0; j < 4; j++) acc[i][j] = 0.f;
    int tr = (tid >> 4) << 2;
    int tc = (tid & 15) << 2;
    for (int k0 = 0; k0 < K; k0 += 16) {
        #pragma unroll
        for (int i = 0; i < 4; i++) {
            int idx = tid + 256 * i;
            int r = idx >> 4, kk = idx & 15;
            int gr = row0 + r;
            As[r][kk] = (gr < M) ? A[(size_t)gr * K + k0 + kk] : 0.f;
        }
        #pragma unroll
        for (int i = 0; i < 4; i++) {
            int idx = tid + 256 * i;
            int kk = idx >> 6, c = idx & 63;
            int gc = col0 + c;
            Bs[kk][c] = (gc < N) ? Bz[(size_t)(k0 + kk) * N + gc] : 0.f;
        }
        __syncthreads();
        #pragma unroll
        for (int kk = 0; kk < 16; kk++) {
            float a0 = As[tr + 0][kk];
            float a1 = As[tr + 1][kk];
            float a2 = As[tr + 2][kk];
            float a3 = As[tr + 3][kk];
            float4 bb = *reinterpret_cast<const float4*>(&Bs[kk][tc]);
            acc[0][0] += a0 * bb.x; acc[0][1] += a0 * bb.y; acc[0][2] += a0 * bb.z; acc[0][3] += a0 * bb.w;
            acc[1][0] += a1 * bb.x; acc[1][1] += a1 * bb.y; acc[1][2] += a1 * bb.z; acc[1][3] += a1 * bb.w;
            acc[2][0] += a2 * bb.x; acc[2][1] += a2 * bb.y; acc[2][2] += a2 * bb.z; acc[2][3] += a2 * bb.w;
            acc[3][0] += a3 * bb.x; acc[3][1] += a3 * bb.y; acc[3][2] += a3 * bb.z; acc[3][3] += a3 * bb.w;
        }
        __syncthreads();
    }
    #pragma unroll
    for (int i = 0; i < 4; i++) {
        int gr = row0 + tr + i;
        if (gr >= M) continue;
        float bv = bias ? bias[gr] : 0.f;
        #pragma unroll
        for (int j = 0; j < 4; j++) {
            int gc = col0 + tc + j;
            if (gc < N) Cz[(size_t)gr * N + gc] = acc[i][j] + bv;
        }
    }
}

// ---------------------------------------------------------------------------
// Host launcher
// ---------------------------------------------------------------------------
extern "C" void kernel_launch(void* const* d_in, const int* in_sizes, int n_in,
                              void* d_out, int out_size) {
    const float* input = (const float*)d_in[0];
    const float* objects = (const float*)d_in[1];
    // d_in[2] = objects_length (unused; uniform n)
    const float* Wc   = (const float*)d_in[3];
    const float* bc   = (const float*)d_in[4];
    const float* Wr   = (const float*)d_in[5];
    const float* br   = (const float*)d_in[6];
    const float* Wof  = (const float*)d_in[7];
    const float* bof  = (const float*)d_in[8];
    const float* Wrf  = (const float*)d_in[9];
    const float* brf  = (const float*)d_in[10];
    const float* Wofc = (const float*)d_in[11];
    const float* bofc = (const float*)d_in[12];
    const float* Wrfc = (const float*)d_in[13];
    const float* brfc = (const float*)d_in[14];
    float* out = (float*)d_out;

    float *p_ctx, *p_relf, *p_obj_in, *p_obj_feat, *p_rel_in, *p_rel_feat;
    float *p_act_obj, *p_act_rel, *p_out_obj, *p_out_rel;
    cudaGetSymbolAddress((void**)&p_ctx,      g_ctx);
    cudaGetSymbolAddress((void**)&p_relf,     g_relf);
    cudaGetSymbolAddress((void**)&p_obj_in,   g_obj_in);
    cudaGetSymbolAddress((void**)&p_obj_feat, g_obj_feat);
    cudaGetSymbolAddress((void**)&p_rel_in,   g_rel_in);
    cudaGetSymbolAddress((void**)&p_rel_feat, g_rel_feat);
    cudaGetSymbolAddress((void**)&p_act_obj,  g_act_obj);
    cudaGetSymbolAddress((void**)&p_act_rel,  g_act_rel);
    cudaGetSymbolAddress((void**)&p_out_obj,  g_out_obj);
    cudaGetSymbolAddress((void**)&p_out_rel,  g_out_rel);

    // 1) ctx = Wc @ input  (per image), 2) rel = Wr @ input
    {
        dim3 g(HW_ / 64, C_ / 64, B_);
        sgemm<<<g, 256>>>(Wc, input, bc, p_ctx, C_, HW_, C_,
                          (long long)C_ * HW_, (long long)C_ * HW_);
    }
    {
        dim3 g(HW_ / 64, CREL / 64, B_);
        sgemm<<<g, 256>>>(Wr, input, br, p_relf, CREL, HW_, C_,
                          (long long)C_ * HW_, (long long)CREL * HW_);
    }

    // 3) ROI weights + intersection maps (independent of convs)
    k_roi_weights<<<NROI_TOT, 256>>>(objects);
    k_imaps<<<NROI_OBJ + NROI_UN, 64>>>(objects);

    // 4) ctx pooled over image box
    k_ctx_pool<<<B_ * C_, 224>>>();

    // 5) object pooling of raw input -> g_obj_in rows 0..255
    k_obj_pool<<<NROI_OBJ * C_, 224>>>(input);

    // 6) ctx rows of obj_in (256..511)
    {
        int total = 256 * NPQ_OBJ;
        k_fill_obj_ctx<<<(total + 255) / 256, 256>>>();
    }

    // 7) obj_feat = Wof @ obj_in + bof
    {
        dim3 g(NPQ_OBJ / 64, D1_ / 64, 1);
        sgemm<<<g, 256>>>(Wof, p_obj_in, bof, p_obj_feat, D1_, NPQ_OBJ, KOBJ, 0, 0);
    }

    // 8) union pooling of rel features -> g_rel_in rows 512..895
    k_rel_pool<<<NROI_UN * CREL, 224>>>();

    // 9) gather obj_feat pairs -> g_rel_in rows 0..511
    {
        size_t total = (size_t)512 * NPQ_UN;
        k_gather_objfeat<<<(unsigned)((total + 255) / 256), 256>>>();
    }

    // 10) rel_feat = Wrf @ rel_in + brf
    {
        dim3 g(NPQ_UN / 64, D2_ / 64, 1);
        sgemm<<<g, 256>>>(Wrf, p_rel_in, brf, p_rel_feat, D2_, NPQ_UN, KREL, 0, 0);
    }

    // 11) final obj FC: relu+repack then GEMM [256,12544]x[12544,128]
    {
        dim3 g(D1_, NROI_OBJ / 32);
        k_repack<<<g, 256>>>(p_obj_feat, p_act_obj, NROI_OBJ);
    }
    {
        dim3 g(NROI_OBJ / 64, D1_ / 64, 1);
        sgemm<<<g, 256>>>(Wofc, p_act_obj, bofc, p_out_obj, D1_, NROI_OBJ, KFC, 0, 0);
    }

    // 12) final rel FC
    {
        dim3 g(D2_, NROI_UN / 32);
        k_repack<<<g, 256>>>(p_rel_feat, p_act_rel, NROI_UN);
    }
    {
        dim3 g(NROI_UN / 64, D2_ / 64, 1);
        sgemm<<<g, 256>>>(Wrfc, p_act_rel, brfc, p_out_rel, D2_, NROI_UN, KFC, 0, 0);
    }

    // 13) L2 normalize and emit: obj first [8,16,256], then rel [8,16,16,256]
    k_normalize<<<NROI_OBJ, 256>>>(p_out_obj, out, NROI_OBJ);
    k_normalize<<<NROI_UN, 256>>>(p_out_rel, out + OBJ_OUT_SZ, NROI_UN);
}

// round 3
// speedup vs baseline: 2.5286x; 2.5286x over previous
#include <cuda_runtime.h>
#include <cstdint>

// ---------------------------------------------------------------------------
// Problem constants (fixed shapes from setup_inputs)
// ---------------------------------------------------------------------------
#define B_       8
#define C_       256
#define HW_      1024
#define NOBJ     16
#define P_       7
#define PQ_      49
#define NROI_OBJ 128            // B_*NOBJ
#define NPAIR    256            // NOBJ*NOBJ
#define NROI_UN  2048           // B_*NPAIR
#define CREL     384            // C/2*3
#define D1_      256
#define D2_      256
#define KOBJ     512            // 2*C
#define KREL     896            // 2*D1 + CREL
#define NPQ_OBJ  (NROI_OBJ*PQ_) // 6272
#define NPQ_UN   (NROI_UN*PQ_)  // 100352
#define KFC      (256*PQ_)      // 12544
#define NROI_TOT (1 + NROI_OBJ + NROI_UN) // 2177
#define OBJ_OUT_SZ (NROI_OBJ*D1_)         // 32768
#define NSPLIT_OBJ 32
#define NSPLIT_REL 16

// ---------------------------------------------------------------------------
// Device scratch (static only)
// ---------------------------------------------------------------------------
__device__ float g_ctx     [B_*C_*HW_];
__device__ float g_relf    [B_*CREL*HW_];
__device__ float g_wx      [NROI_TOT*P_*32];
__device__ float g_wy      [NROI_TOT*P_*32];
__device__ float g_inv_area[NROI_TOT];
__device__ float g_ctx_pool[B_*C_*PQ_];
__device__ float g_box_imap[NROI_OBJ*PQ_];
__device__ float g_sub_imap[NROI_UN*PQ_];
__device__ float g_obj_imap[NROI_UN*PQ_];
__device__ float g_obj_in  [(size_t)KOBJ*NPQ_OBJ];
__device__ float g_obj_feat[(size_t)D1_*NPQ_OBJ];
__device__ float g_rel_in  [(size_t)KREL*NPQ_UN];
__device__ float g_rel_feat[(size_t)D2_*NPQ_UN];
__device__ float g_act_obj [(size_t)KFC*NROI_OBJ];
__device__ float g_act_rel [(size_t)KFC*NROI_UN];
__device__ float g_part_obj[(size_t)NSPLIT_OBJ*D1_*NROI_OBJ];
__device__ float g_part_rel[(size_t)NSPLIT_REL*D2_*NROI_UN];
__device__ float g_out_obj [(size_t)D1_*NROI_OBJ];
__device__ float g_out_rel [(size_t)D2_*NROI_UN];

// ---------------------------------------------------------------------------
// Packed f32x2 helpers (Blackwell FFMA2 path)
// ---------------------------------------------------------------------------
__device__ __forceinline__ unsigned long long pack2(float x, float y) {
    unsigned long long r;
    asm("mov.b64 %0, {%1, %2};" : "=l"(r) : "r"(__float_as_uint(x)), "r"(__float_as_uint(y)));
    return r;
}
__device__ __forceinline__ void fma2(unsigned long long& acc, unsigned long long a,
                                     unsigned long long b) {
    asm("fma.rn.f32x2 %0, %1, %2, %0;" : "+l"(acc) : "l"(a), "l"(b));
}
__device__ __forceinline__ void unpack2(unsigned long long v, float& x, float& y) {
    unsigned lo, hi;
    asm("mov.b64 {%0, %1}, %2;" : "=r"(lo), "=r"(hi) : "l"(v));
    x = __uint_as_float(lo); y = __uint_as_float(hi);
}

// ---------------------------------------------------------------------------
// Misc helpers
// ---------------------------------------------------------------------------
__device__ __forceinline__ float hat_int(float t) {
    t = fminf(fmaxf(t, -1.f), 1.f);
    float u  = 1.f - t;
    float r0 = 0.5f * (t + 1.f) * (t + 1.f);
    float r1 = 1.f - 0.5f * u * u;
    return (t < 0.f) ? r0 : r1;
}
__device__ __forceinline__ float imap_frac(float b1x0, float b1y0, float b1x1, float b1y1,
                                           float b2x0, float b2y0, float b2x1, float b2y1,
                                           int p, int q) {
    float bw = (b2x1 - b2x0) / 7.f;
    float bh = (b2y1 - b2y0) / 7.f;
    float gx0 = b2x0 + bw * (float)q;
    float gy0 = b2y0 + bh * (float)p;
    float ox = fmaxf(0.f, fminf(gx0 + bw, b1x1) - fmaxf(gx0, b1x0));
    float oy = fmaxf(0.f, fminf(gy0 + bh, b1y1) - fmaxf(gy0, b1y0));
    return oy * ox / fmaxf(bw * bh, 1e-8f);
}

// ---------------------------------------------------------------------------
// ROI integration weights
// ---------------------------------------------------------------------------
__global__ void k_roi_weights(const float* __restrict__ objects) {
    int roi = blockIdx.x;
    float b0, b1, b2, b3;
    if (roi == 0) {
        b0 = 0.f; b1 = 0.f; b2 = 512.f; b3 = 512.f;
    } else if (roi <= NROI_OBJ) {
        const float* o = objects + (roi - 1) * 4;
        b0 = o[0]; b1 = o[1]; b2 = o[2]; b3 = o[3];
    } else {
        int u  = roi - (1 + NROI_OBJ);
        int b  = u / NPAIR;
        int pi = u % NPAIR;
        int i  = pi / NOBJ, j = pi % NOBJ;
        const float* s = objects + (b * NOBJ + i) * 4;
        const float* o = objects + (b * NOBJ + j) * 4;
        b0 = fminf(s[0], o[0]); b1 = fminf(s[1], o[1]);
        b2 = fmaxf(s[2], o[2]); b3 = fmaxf(s[3], o[3]);
    }
    const float sc = 1.f / 16.f;
    float lx = b0 * sc, hx = b2 * sc, ly = b1 * sc, hy = b3 * sc;
    float bwx = (hx - lx) / 7.f;
    float bwy = (hy - ly) / 7.f;
    int t = threadIdx.x;
    if (t < P_ * 32) {
        int p = t / 32, i = t % 32;
        float sx = lx + bwx * (float)p, ex = sx + bwx;
        g_wx[roi * 224 + t] = hat_int(ex - (float)i) - hat_int(sx - (float)i);
        float sy = ly + bwy * (float)p, ey = sy + bwy;
        g_wy[roi * 224 + t] = hat_int(ey - (float)i) - hat_int(sy - (float)i);
    }
    if (t == 0) g_inv_area[roi] = 1.f / fmaxf(bwx * bwy, 1e-8f);
}

__global__ void k_imaps(const float* __restrict__ objects) {
    int bid = blockIdx.x;
    int t = threadIdx.x;
    if (t >= PQ_) return;
    int p = t / P_, q = t % P_;
    if (bid < NROI_OBJ) {
        const float* o = objects + bid * 4;
        g_box_imap[bid * PQ_ + t] =
            imap_frac(o[0], o[1], o[2], o[3], 0.f, 0.f, 512.f, 512.f, p, q);
    } else {
        int u  = bid - NROI_OBJ;
        int b  = u / NPAIR;
        int pi = u % NPAIR;
        int i  = pi / NOBJ, j = pi % NOBJ;
        const float* s = objects + (b * NOBJ + i) * 4;
        const float* o = objects + (b * NOBJ + j) * 4;
        float ux0 = fminf(s[0], o[0]), uy0 = fminf(s[1], o[1]);
        float ux1 = fmaxf(s[2], o[2]), uy1 = fmaxf(s[3], o[3]);
        g_sub_imap[u * PQ_ + t] =
            imap_frac(s[0], s[1], s[2], s[3], ux0, uy0, ux1, uy1, p, q);
        g_obj_imap[u * PQ_ + t] =
            imap_frac(o[0], o[1], o[2], o[3], ux0, uy0, ux1, uy1, p, q);
    }
}

// ---------------------------------------------------------------------------
// Warp-autonomous PrRoI pooling core.
// src: channel base [32x32], swy/swx: padded (stride 36) weights in smem,
// slab: per-warp 256-float smem scratch. Returns o0 for pq=lane, o1 for pq=lane+32.
// ---------------------------------------------------------------------------
__device__ __forceinline__ void warp_pool(const float* __restrict__ src,
                                          const float* swy, const float* swx,
                                          float* slab, int lane,
                                          float& o0, float& o1) {
    float v[32];
    #pragma unroll
    for (int h = 0; h < 32; h++) v[h] = __ldg(src + h * 32 + lane);
    #pragma unroll
    for (int p = 0; p < 7; p++) {
        float s = 0.f;
        #pragma unroll
        for (int h4 = 0; h4 < 8; h4++) {
            float4 w4 = *reinterpret_cast<const float4*>(&swy[p * 36 + h4 * 4]);
            s += v[h4*4+0]*w4.x + v[h4*4+1]*w4.y + v[h4*4+2]*w4.z + v[h4*4+3]*w4.w;
        }
        slab[p * 36 + lane] = s;
    }
    __syncwarp();
    {
        int p = lane / 7, q = lane % 7;   // pq0 = lane (< 49 always)
        float s = 0.f;
        #pragma unroll
        for (int w4 = 0; w4 < 8; w4++) {
            float4 t4 = *reinterpret_cast<const float4*>(&slab[p * 36 + w4 * 4]);
            float4 x4 = *reinterpret_cast<const float4*>(&swx[q * 36 + w4 * 4]);
            s += t4.x*x4.x + t4.y*x4.y + t4.z*x4.z + t4.w*x4.w;
        }
        o0 = s;
    }
    o1 = 0.f;
    int pq1 = lane + 32;
    if (pq1 < PQ_) {
        int p = pq1 / 7, q = pq1 % 7;
        float s = 0.f;
        #pragma unroll
        for (int w4 = 0; w4 < 8; w4++) {
            float4 t4 = *reinterpret_cast<const float4*>(&slab[p * 36 + w4 * 4]);
            float4 x4 = *reinterpret_cast<const float4*>(&swx[q * 36 + w4 * 4]);
            s += t4.x*x4.x + t4.y*x4.y + t4.z*x4.z + t4.w*x4.w;
        }
        o1 = s;
    }
    __syncwarp();
}

// ctx pool: grid = B_*C_/8 blocks of 256 threads (8 warps, one channel each)
__global__ void k_pool_ctx() {
    __shared__ __align__(16) float swy[256], swx[256];
    __shared__ __align__(16) float slab[8][256];
    int t = threadIdx.x;
    if (t < 224) { int p = t / 32, i = t % 32;
        swy[p*36+i] = g_wy[t]; swx[p*36+i] = g_wx[t]; }
    __syncthreads();
    int warp = t >> 5, lane = t & 31;
    int task = blockIdx.x * 8 + warp;     // b*256 + c
    float o0, o1;
    warp_pool(g_ctx + (size_t)task * HW_, swy, swx, slab[warp], lane, o0, o1);
    float ia = g_inv_area[0];
    g_ctx_pool[(size_t)task * PQ_ + lane] = o0 * ia;
    if (lane + 32 < PQ_) g_ctx_pool[(size_t)task * PQ_ + lane + 32] = o1 * ia;
}

// obj pool: grid = NROI_OBJ * (C_/8) blocks
__global__ void k_pool_obj(const float* __restrict__ input) {
    __shared__ __align__(16) float swy[256], swx[256];
    __shared__ __align__(16) float slab[8][256];
    int rg = blockIdx.x >> 5;
    int cg = blockIdx.x & 31;
    int roi = 1 + rg;
    int t = threadIdx.x;
    if (t < 224) { int p = t / 32, i = t % 32;
        swy[p*36+i] = g_wy[roi*224 + t]; swx[p*36+i] = g_wx[roi*224 + t]; }
    __syncthreads();
    int warp = t >> 5, lane = t & 31;
    int c = cg * 8 + warp;
    int b = rg >> 4;
    float o0, o1;
    warp_pool(input + ((size_t)(b * C_ + c)) * HW_, swy, swx, slab[warp], lane, o0, o1);
    float ia = g_inv_area[roi];
    g_obj_in[(size_t)c * NPQ_OBJ + rg * PQ_ + lane] = o0 * ia;
    if (lane + 32 < PQ_)
        g_obj_in[(size_t)c * NPQ_OBJ + rg * PQ_ + lane + 32] = o1 * ia;
}

// rel pool: grid = NROI_UN * (CREL/8) blocks
__global__ void k_pool_rel() {
    __shared__ __align__(16) float swy[256], swx[256];
    __shared__ __align__(16) float slab[8][256];
    __shared__ float s_sub[PQ_], s_obj[PQ_];
    int ru = blockIdx.x / 48;
    int cg = blockIdx.x % 48;
    int roi = 1 + NROI_OBJ + ru;
    int t = threadIdx.x;
    if (t < 224) { int p = t / 32, i = t % 32;
        swy[p*36+i] = g_wy[roi*224 + t]; swx[p*36+i] = g_wx[roi*224 + t]; }
    if (t < PQ_) { s_sub[t] = g_sub_imap[ru * PQ_ + t]; s_obj[t] = g_obj_imap[ru * PQ_ + t]; }
    __syncthreads();
    int warp = t >> 5, lane = t & 31;
    int c = cg * 8 + warp;
    int b = ru >> 8;
    float o0, o1;
    warp_pool(g_relf + ((size_t)(b * CREL + c)) * HW_, swy, swx, slab[warp], lane, o0, o1);
    float ia = g_inv_area[roi];
    o0 *= ia; o1 *= ia;
    if (c >= 256)      { o0 *= s_obj[lane]; if (lane + 32 < PQ_) o1 *= s_obj[lane + 32]; }
    else if (c >= 128) { o0 *= s_sub[lane]; if (lane + 32 < PQ_) o1 *= s_sub[lane + 32]; }
    size_t base = (size_t)(512 + c) * NPQ_UN + (size_t)ru * PQ_;
    g_rel_in[base + lane] = o0;
    if (lane + 32 < PQ_) g_rel_in[base + lane + 32] = o1;
}

// Fill g_obj_in rows 256..511 from ctx_pool (+ box_imap on y half)
__global__ void k_fill_obj_ctx() {
    int idx = blockIdx.x * blockDim.x + threadIdx.x;
    if (idx >= 256 * NPQ_OBJ) return;
    int c2 = idx / NPQ_OBJ;
    int nn = idx % NPQ_OBJ;
    int rg = nn / PQ_, pq = nn % PQ_;
    int b  = rg / NOBJ;
    float v = g_ctx_pool[((size_t)b * C_ + c2) * PQ_ + pq];
    if (c2 >= 128) v *= g_box_imap[rg * PQ_ + pq];
    g_obj_in[((size_t)(256 + c2)) * NPQ_OBJ + nn] = v;
}

// Gather obj_feat pairs into g_rel_in rows 0..511
__global__ void k_gather_objfeat() {
    size_t idx = (size_t)blockIdx.x * blockDim.x + threadIdx.x;
    if (idx >= (size_t)512 * NPQ_UN) return;
    int d2 = (int)(idx / NPQ_UN);
    int nu = (int)(idx % NPQ_UN);
    int ru = nu / PQ_, pq = nu % PQ_;
    int b  = ru / NPAIR;
    int pi = ru % NPAIR;
    int r  = (d2 < 256) ? (pi / NOBJ) : (pi % NOBJ);
    int d  = d2 & 255;
    g_rel_in[idx] = g_obj_feat[(size_t)d * NPQ_OBJ + (b * NOBJ + r) * PQ_ + pq];
}

// ReLU + transpose repack: in [256][R*49] -> out [256*49][R]
__global__ void k_repack(const float* __restrict__ in, float* __restrict__ out, int R) {
    __shared__ float s[32 * PQ_];
    int d  = blockIdx.x;
    int r0 = blockIdx.y * 32;
    const float* src = in + (size_t)d * R * PQ_ + (size_t)r0 * PQ_;
    for (int i = threadIdx.x; i < 32 * PQ_; i += blockDim.x)
        s[i] = fmaxf(0.f, src[i]);
    __syncthreads();
    for (int i = threadIdx.x; i < 32 * PQ_; i += blockDim.x) {
        int pq = i / 32, r = i % 32;
        out[((size_t)d * PQ_ + pq) * R + r0 + r] = s[r * PQ_ + pq];
    }
}

// Reduce split-K partials + bias: out[m*N+n] = bias[m] + sum_z part[z][m][n]
__global__ void k_reduce(const float* __restrict__ part, const float* __restrict__ bias,
                         float* __restrict__ out, int MN, int N, int nsplit) {
    int idx = blockIdx.x * blockDim.x + threadIdx.x;
    if (idx >= MN) return;
    float s = bias[idx / N];
    for (int z = 0; z < nsplit; z++) s += part[(size_t)z * MN + idx];
    out[idx] = s;
}

// L2 normalize columns of M[256][R]; out rows [r][256]
__global__ void k_normalize(const float* __restrict__ M, float* __restrict__ out, int R) {
    __shared__ float red[256];
    int r = blockIdx.x;
    int e = threadIdx.x;
    float v = M[(size_t)e * R + r];
    red[e] = v * v;
    __syncthreads();
    for (int s = 128; s > 0; s >>= 1) {
        if (e < s) red[e] += red[e + s];
        __syncthreads();
    }
    out[(size_t)r * 256 + e] = v * rsqrtf(red[0]);
}

// ---------------------------------------------------------------------------
// 128x128x8 double-buffered SGEMM with packed f32x2 FMA.
// C[M][N] = A[M][K(ld)] * B[K][N] (+ bias[M]).
// All of M%128, N%128, kLen%8 must hold (true for every call here).
// splitK==0: z = batch (A/bias shared, B/C strided).
// splitK==1: z = K-chunk; kStart=z*kLen; C -> C + z*M*N; no bias.
// ---------------------------------------------------------------------------
__global__ void sgemm128(const float* __restrict__ A, const float* __restrict__ B,
                         const float* __restrict__ bias, float* __restrict__ C,
                         int M, int N, int K, int kLen,
                         long long sB, long long sC, int splitK) {
    const float* Bz;
    float* Cz;
    int kStart;
    if (splitK) {
        Bz = B; Cz = C + (size_t)blockIdx.z * M * N; kStart = blockIdx.z * kLen;
    } else {
        Bz = B + (long long)blockIdx.z * sB; Cz = C + (long long)blockIdx.z * sC; kStart = 0;
    }
    __shared__ __align__(16) float As[2][8][128];
    __shared__ __align__(16) float Bs[2][8][128];
    int tid  = threadIdx.x;
    int row0 = blockIdx.y * 128, col0 = blockIdx.x * 128;
    int arow = tid >> 1;
    int acol = (tid & 1) * 4;
    int brow = tid >> 5;
    int bcol = (tid & 31) * 4;
    int tx = tid & 15, ty = tid >> 4;

    unsigned long long acc[8][4];
    #pragma unroll
    for (int i = 0; i < 8; i++)
        #pragma unroll
        for (int j = 0; j < 4; j++) acc[i][j] = 0ull;

    // prologue
    {
        float4 ra = *reinterpret_cast<const float4*>(&A[(size_t)(row0 + arow) * K + kStart + acol]);
        float4 rb = *reinterpret_cast<const float4*>(&Bz[(size_t)(kStart + brow) * N + col0 + bcol]);
        As[0][acol+0][arow] = ra.x; As[0][acol+1][arow] = ra.y;
        As[0][acol+2][arow] = ra.z; As[0][acol+3][arow] = ra.w;
        *reinterpret_cast<float4*>(&Bs[0][brow][bcol]) = rb;
    }
    __syncthreads();

    int nk = kLen / 8;
    for (int t = 0; t < nk; t++) {
        int cur = t & 1;
        bool more = (t + 1) < nk;
        float4 na, nb;
        if (more) {
            na = *reinterpret_cast<const float4*>(&A[(size_t)(row0 + arow) * K + kStart + (t+1)*8 + acol]);
            nb = *reinterpret_cast<const float4*>(&Bz[(size_t)(kStart + (t+1)*8 + brow) * N + col0 + bcol]);
        }
        #pragma unroll
        for (int kk = 0; kk < 8; kk++) {
            float4 a0 = *reinterpret_cast<const float4*>(&As[cur][kk][ty * 4]);
            float4 a1 = *reinterpret_cast<const float4*>(&As[cur][kk][ty * 4 + 64]);
            float4 b0 = *reinterpret_cast<const float4*>(&Bs[cur][kk][tx * 4]);
            float4 b1 = *reinterpret_cast<const float4*>(&Bs[cur][kk][tx * 4 + 64]);
            unsigned long long bp0 = pack2(b0.x, b0.y);
            unsigned long long bp1 = pack2(b0.z, b0.w);
            unsigned long long bp2 = pack2(b1.x, b1.y);
            unsigned long long bp3 = pack2(b1.z, b1.w);
            float av[8] = {a0.x, a0.y, a0.z, a0.w, a1.x, a1.y, a1.z, a1.w};
            #pragma unroll
            for (int i = 0; i < 8; i++) {
                unsigned long long ap = pack2(av[i], av[i]);
                fma2(acc[i][0], ap, bp0);
                fma2(acc[i][1], ap, bp1);
                fma2(acc[i][2], ap, bp2);
                fma2(acc[i][3], ap, bp3);
            }
        }
        if (more) {
            int nxt = cur ^ 1;
            As[nxt][acol+0][arow] = na.x; As[nxt][acol+1][arow] = na.y;
            As[nxt][acol+2][arow] = na.z; As[nxt][acol+3][arow] = na.w;
            *reinterpret_cast<float4*>(&Bs[nxt][brow][bcol]) = nb;
            __syncthreads();
        }
    }

    #pragma unroll
    for (int i = 0; i < 8; i++) {
        int r = row0 + ty * 4 + (i < 4 ? i : 64 + (i - 4));
        float bv = (bias != nullptr) ? bias[r] : 0.f;
        float4 o;
        unpack2(acc[i][0], o.x, o.y);
        unpack2(acc[i][1], o.z, o.w);
        o.x += bv; o.y += bv; o.z += bv; o.w += bv;
        *reinterpret_cast<float4*>(&Cz[(size_t)r * N + col0 + tx * 4]) = o;
        unpack2(acc[i][2], o.x, o.y);
        unpack2(acc[i][3], o.z, o.w);
        o.x += bv; o.y += bv; o.z += bv; o.w += bv;
        *reinterpret_cast<float4*>(&Cz[(size_t)r * N + col0 + tx * 4 + 64]) = o;
    }
}

// ---------------------------------------------------------------------------
// Host launcher
// ---------------------------------------------------------------------------
extern "C" void kernel_launch(void* const* d_in, const int* in_sizes, int n_in,
                              void* d_out, int out_size) {
    const float* input   = (const float*)d_in[0];
    const float* objects = (const float*)d_in[1];
    const float* Wc   = (const float*)d_in[3];
    const float* bc   = (const float*)d_in[4];
    const float* Wr   = (const float*)d_in[5];
    const float* br   = (const float*)d_in[6];
    const float* Wof  = (const float*)d_in[7];
    const float* bof  = (const float*)d_in[8];
    const float* Wrf  = (const float*)d_in[9];
    const float* brf  = (const float*)d_in[10];
    const float* Wofc = (const float*)d_in[11];
    const float* bofc = (const float*)d_in[12];
    const float* Wrfc = (const float*)d_in[13];
    const float* brfc = (const float*)d_in[14];
    float* out = (float*)d_out;

    float *p_ctx, *p_relf, *p_obj_in, *p_obj_feat, *p_rel_in, *p_rel_feat;
    float *p_act_obj, *p_act_rel, *p_part_obj, *p_part_rel, *p_out_obj, *p_out_rel;
    cudaGetSymbolAddress((void**)&p_ctx,      g_ctx);
    cudaGetSymbolAddress((void**)&p_relf,     g_relf);
    cudaGetSymbolAddress((void**)&p_obj_in,   g_obj_in);
    cudaGetSymbolAddress((void**)&p_obj_feat, g_obj_feat);
    cudaGetSymbolAddress((void**)&p_rel_in,   g_rel_in);
    cudaGetSymbolAddress((void**)&p_rel_feat, g_rel_feat);
    cudaGetSymbolAddress((void**)&p_act_obj,  g_act_obj);
    cudaGetSymbolAddress((void**)&p_act_rel,  g_act_rel);
    cudaGetSymbolAddress((void**)&p_part_obj, g_part_obj);
    cudaGetSymbolAddress((void**)&p_part_rel, g_part_rel);
    cudaGetSymbolAddress((void**)&p_out_obj,  g_out_obj);
    cudaGetSymbolAddress((void**)&p_out_rel,  g_out_rel);

    // 1x1 convs: ctx = Wc@input, rel = Wr@input (batched over images)
    {
        dim3 g(HW_ / 128, C_ / 128, B_);
        sgemm128<<<g, 256>>>(Wc, input, bc, p_ctx, C_, HW_, C_, C_,
                             (long long)C_ * HW_, (long long)C_ * HW_, 0);
    }
    {
        dim3 g(HW_ / 128, CREL / 128, B_);
        sgemm128<<<g, 256>>>(Wr, input, br, p_relf, CREL, HW_, C_, C_,
                             (long long)C_ * HW_, (long long)CREL * HW_, 0);
    }

    // ROI weights + intersection maps
    k_roi_weights<<<NROI_TOT, 256>>>(objects);
    k_imaps<<<NROI_OBJ + NROI_UN, 64>>>(objects);

    // pooling
    k_pool_ctx<<<B_ * C_ / 8, 256>>>();
    k_pool_obj<<<NROI_OBJ * (C_ / 8), 256>>>(input);

    // obj_in ctx rows
    k_fill_obj_ctx<<<(256 * NPQ_OBJ + 255) / 256, 256>>>();

    // obj_feat = Wof @ obj_in + bof
    {
        dim3 g(NPQ_OBJ / 128, D1_ / 128, 1);
        sgemm128<<<g, 256>>>(Wof, p_obj_in, bof, p_obj_feat, D1_, NPQ_OBJ, KOBJ, KOBJ, 0, 0, 0);
    }

    // union pooling (rows 512..895 of rel_in)
    k_pool_rel<<<NROI_UN * (CREL / 8), 256>>>();

    // gather obj_feat pairs (rows 0..511)
    {
        size_t total = (size_t)512 * NPQ_UN;
        k_gather_objfeat<<<(unsigned)((total + 255) / 256), 256>>>();
    }

    // rel_feat = Wrf @ rel_in + brf
    {
        dim3 g(NPQ_UN / 128, D2_ / 128, 1);
        sgemm128<<<g, 256>>>(Wrf, p_rel_in, brf, p_rel_feat, D2_, NPQ_UN, KREL, KREL, 0, 0, 0);
    }

    // final obj FC (split-K)
    {
        dim3 g(D1_, NROI_OBJ / 32);
        k_repack<<<g, 256>>>(p_obj_feat, p_act_obj, NROI_OBJ);
    }
    {
        dim3 g(NROI_OBJ / 128, D1_ / 128, NSPLIT_OBJ);
        sgemm128<<<g, 256>>>(Wofc, p_act_obj, nullptr, p_part_obj,
                             D1_, NROI_OBJ, KFC, KFC / NSPLIT_OBJ, 0, 0, 1);
        k_reduce<<<(D1_ * NROI_OBJ + 255) / 256, 256>>>(p_part_obj, bofc, p_out_obj,
                                                        D1_ * NROI_OBJ, NROI_OBJ, NSPLIT_OBJ);
    }

    // final rel FC (split-K)
    {
        dim3 g(D2_, NROI_UN / 32);
        k_repack<<<g, 256>>>(p_rel_feat, p_act_rel, NROI_UN);
    }
    {
        dim3 g(NROI_UN / 128, D2_ / 128, NSPLIT_REL);
        sgemm128<<<g, 256>>>(Wrfc, p_act_rel, nullptr, p_part_rel,
                             D2_, NROI_UN, KFC, KFC / NSPLIT_REL, 0, 0, 1);
        k_reduce<<<(D2_ * NROI_UN + 255) / 256, 256>>>(p_part_rel, brfc, p_out_rel,
                                                       D2_ * NROI_UN, NROI_UN, NSPLIT_REL);
    }

    // normalize + emit
    k_normalize<<<NROI_OBJ, 256>>>(p_out_obj, out, NROI_OBJ);
    k_normalize<<<NROI_UN, 256>>>(p_out_rel, out + OBJ_OUT_SZ, NROI_UN);
}